// round 3
// baseline (speedup 1.0000x reference)
#include <cuda_runtime.h>
#include <cuda_bf16.h>
#include <cstddef>

// Problem constants (fixed by setup_inputs)
#define T_DIM   2
#define C_DIM   3
#define OUT_HW  532            // output height/width
#define PW_DIM  536            // patches per row/col
#define HW_PATCH (PW_DIM * PW_DIM)   // 287296
#define PDIM    75
#define PS      5

// Tiling
#define TX      38             // output columns per block (532 = 14*38)
#define XT      14
#define YT      14
#define ROWS    38             // output rows per block (532 = 14*38)
#define NP      (TX + 4)       // 42 patches per loaded row
#define SROW    77             // padded floats per patch slot (75 wd + w@75, pad->77)
#define SMEM_FLOATS (5 * NP * SROW)           // 16170
#define SMEM_BYTES  (SMEM_FLOATS * 4)         // 64680

#define IMG_PIX (OUT_HW * OUT_HW)             // 283024

__device__ float g_partials[6 * 32];
__device__ float g_means[6];

// ---------------- mean reduction (deterministic, 2-stage) ----------------
__global__ void mean_stage1(const float* __restrict__ noisy) {
    // grid = 6*32 blocks, 256 threads
    int tc  = blockIdx.x >> 5;      // (t*3 + c)
    int seg = blockIdx.x & 31;
    const float* base = noisy + (size_t)tc * IMG_PIX;
    const int per = (IMG_PIX + 31) / 32;     // 8845
    int start = seg * per;
    int end   = start + per;
    if (end > IMG_PIX) end = IMG_PIX;
    float s = 0.f;
    for (int i = start + threadIdx.x; i < end; i += 256)
        s += base[i];
    __shared__ float red[256];
    red[threadIdx.x] = s;
    __syncthreads();
    for (int o = 128; o > 0; o >>= 1) {
        if (threadIdx.x < o) red[threadIdx.x] += red[threadIdx.x + o];
        __syncthreads();
    }
    if (threadIdx.x == 0) g_partials[blockIdx.x] = red[0];
}

__global__ void mean_stage2() {
    // grid = 6 blocks, 32 threads
    float v = g_partials[blockIdx.x * 32 + threadIdx.x];
    #pragma unroll
    for (int o = 16; o > 0; o >>= 1)
        v += __shfl_down_sync(0xffffffffu, v, o);
    if (threadIdx.x == 0) {
        // mean of (x-0.5)/0.5 = 2*mean(x) - 1
        g_means[blockIdx.x] = (v / (float)IMG_PIX - 0.5f) * 2.0f;
    }
}

// ---------------- main fold kernel ----------------
__global__ void __launch_bounds__(128, 3)
fold_kernel(const float* __restrict__ deno,
            const float* __restrict__ pw,
            float* __restrict__ out) {
    extern __shared__ float sm[];   // [5][NP][SROW]

    const int t  = blockIdx.z;
    const int x0 = blockIdx.x * TX;       // output tile start col
    const int y0 = blockIdx.y * ROWS;     // output tile start row
    const int tid = threadIdx.x;          // 128 threads

    const float* denoT = deno + (size_t)t * HW_PATCH * PDIM;
    const float* pwT   = pw   + (size_t)t * HW_PATCH;

    // compute-thread mapping (only tid < 114 compute)
    const int c  = tid / TX;          // 0..2 (3 for idle threads)
    const int lx = tid - c * TX;      // 0..37
    float meanc = 0.f;
    if (c < C_DIM) meanc = g_means[t * 3 + c];

    // -------- row loader: premultiplied deno*w into rolling slot, w at [75]
    auto load_row = [&](int py) {
        const int slot = py % 5;
        float* dst = sm + slot * (NP * SROW);
        const float* src  = denoT + ((size_t)py * PW_DIM + x0) * PDIM;
        const float* wsrc = pwT + (size_t)py * PW_DIM + x0;
        #pragma unroll 5
        for (int e = tid; e < NP * PDIM; e += 128) {
            int p = e / PDIM;
            int k = e - p * PDIM;
            dst[p * SROW + k] = src[e] * __ldg(&wsrc[p]);
        }
        if (tid < NP) dst[tid * SROW + PDIM] = wsrc[tid];
    };

    // preload patch rows y0 .. y0+3
    #pragma unroll
    for (int r = 0; r < 4; ++r) load_row(y0 + r);

    for (int y = y0; y < y0 + ROWS; ++y) {
        const int Y = y + 4;         // canvas row
        load_row(Y);                 // newest row -> slot Y%5
        __syncthreads();

        if (c < C_DIM) {
            float img = 0.f, cnt = 0.f;
            #pragma unroll
            for (int i = 0; i < PS; ++i) {
                const int slot = (Y - i) % 5;
                const float* row = sm + slot * (NP * SROW);
                #pragma unroll
                for (int j = 0; j < PS; ++j) {
                    const float* pp = row + (lx + 4 - j) * SROW;
                    img += pp[c * 25 + i * 5 + j];
                    cnt += pp[PDIM];
                }
            }
            float v = img / cnt + meanc;
            out[(((size_t)t * C_DIM + c) * OUT_HW + y) * OUT_HW + (x0 + lx)]
                = v * 0.5f + 0.5f;
        }
        __syncthreads();   // protect oldest slot before overwrite next iter
    }
}

// ---------------- launch ----------------
extern "C" void kernel_launch(void* const* d_in, const int* in_sizes, int n_in,
                              void* d_out, int out_size) {
    const float* noisy = (const float*)d_in[0];
    const float* deno  = (const float*)d_in[1];
    const float* pw    = (const float*)d_in[2];
    float* out = (float*)d_out;

    cudaFuncSetAttribute(fold_kernel,
                         cudaFuncAttributeMaxDynamicSharedMemorySize,
                         SMEM_BYTES);

    mean_stage1<<<6 * 32, 256>>>(noisy);
    mean_stage2<<<6, 32>>>();

    dim3 grid(XT, YT, T_DIM);
    fold_kernel<<<grid, 128, SMEM_BYTES>>>(deno, pw, out);
}

// round 5
// speedup vs baseline: 2.0373x; 2.0373x over previous
#include <cuda_runtime.h>
#include <cuda_bf16.h>
#include <cstddef>

// Problem constants (fixed by setup_inputs)
#define T_DIM   2
#define C_DIM   3
#define OUT_HW  532
#define PW_DIM  536
#define HW_PATCH (PW_DIM * PW_DIM)     // 287296
#define PDIM    75
#define PS      5
#define IMG_PIX (OUT_HW * OUT_HW)      // 283024

// Pass-1 tiling
#define SEG   128                      // output columns per block
#define NSEG  5                        // ceil(532/128)
#define NPAT  (SEG + 4)                // 132 patches loaded (incl. halo)
#define XPAD  544                      // padded row width for A (544*4 % 128 == 0)

// Intermediate buffers (device globals: no allocation allowed)
__device__ float g_A[(size_t)T_DIM * PW_DIM * C_DIM * PS * XPAD];   // ~33 MB
__device__ float g_Acnt[(size_t)T_DIM * PW_DIM * XPAD];             // ~2.3 MB
__device__ float g_partials[6 * 64];
__device__ float g_means[6];

// ---------------- mean reduction (deterministic, 2-stage, float4) ----------
__global__ void mean_stage1(const float* __restrict__ noisy) {
    // grid = 6*64 blocks, 256 threads. IMG_PIX % 4 == 0, base 16B-aligned.
    const int NV = IMG_PIX / 4;               // 70756 float4 per (t,c)
    int tc  = blockIdx.x >> 6;                // t*3 + c
    int seg = blockIdx.x & 63;
    const float4* base = (const float4*)(noisy + (size_t)tc * IMG_PIX);
    const int per = (NV + 63) / 64;           // 1106
    int start = seg * per;
    int end   = start + per; if (end > NV) end = NV;
    float s = 0.f;
    for (int i = start + threadIdx.x; i < end; i += 256) {
        float4 v = base[i];
        s += (v.x + v.y) + (v.z + v.w);
    }
    __shared__ float red[256];
    red[threadIdx.x] = s;
    __syncthreads();
    for (int o = 128; o > 0; o >>= 1) {
        if (threadIdx.x < o) red[threadIdx.x] += red[threadIdx.x + o];
        __syncthreads();
    }
    if (threadIdx.x == 0) g_partials[blockIdx.x] = red[0];
}

__global__ void mean_stage2() {
    // grid = 6 blocks, 64 threads
    __shared__ float red[64];
    red[threadIdx.x] = g_partials[blockIdx.x * 64 + threadIdx.x];
    __syncthreads();
    if (threadIdx.x < 32) {
        float v = red[threadIdx.x] + red[threadIdx.x + 32];
        #pragma unroll
        for (int o = 16; o > 0; o >>= 1)
            v += __shfl_down_sync(0xffffffffu, v, o);
        if (threadIdx.x == 0)
            g_means[blockIdx.x] = (v / (float)IMG_PIX - 0.5f) * 2.0f;
    }
}

// ---------------- pass 1: horizontal fold ----------------------------------
// A[t, py, c, i, X] = sum_j deno[t, py, X+4-j, c*25+i*5+j] * w[t, py, X+4-j]
// Acnt[t, py, X]    = sum_j w[t, py, X+4-j]
__global__ void __launch_bounds__(128)
pass1_kernel(const float* __restrict__ deno, const float* __restrict__ pw) {
    __shared__ float smd[NPAT * PDIM];   // raw deno, contiguous copy (stride 75)
    __shared__ float smw[NPAT];

    const int t  = blockIdx.z;
    const int py = blockIdx.y;
    const int x0 = blockIdx.x * SEG;
    const int tid = threadIdx.x;

    const int npat = min(NPAT, PW_DIM - x0);            // patches to stage
    const size_t rowbase = (size_t)t * HW_PATCH + (size_t)py * PW_DIM + x0;
    const float* src  = deno + rowbase * PDIM;
    const float* wsrc = pw + rowbase;

    const int tot = npat * PDIM;
    #pragma unroll 4
    for (int e = tid; e < tot; e += 128) smd[e] = src[e];
    // FIX (R4 bug): npat (132) exceeds blockDim (128) -> must grid-stride
    for (int e = tid; e < npat; e += 128) smw[e] = wsrc[e];
    __syncthreads();

    const int nx = min(SEG, OUT_HW - x0);               // active X threads
    if (tid < nx) {
        const int X = x0 + tid;                         // output column
        // tap j uses patch (tid + 4 - j)
        float wr[PS];
        #pragma unroll
        for (int j = 0; j < PS; ++j) wr[j] = smw[tid + 4 - j];
        float cnt = ((wr[0] + wr[1]) + (wr[2] + wr[3])) + wr[4];

        const size_t arow = ((size_t)t * PW_DIM + py);
        g_Acnt[arow * XPAD + X] = cnt;

        const float* b = smd + tid * PDIM;              // patch "tid" base
        #pragma unroll
        for (int c = 0; c < C_DIM; ++c) {
            #pragma unroll
            for (int i = 0; i < PS; ++i) {
                float s = 0.f;
                #pragma unroll
                for (int j = 0; j < PS; ++j) {
                    // element: patch (tid+4-j), word c*25+i*5+j
                    s += b[(4 - j) * PDIM + c * 25 + i * 5 + j] * wr[j];
                }
                g_A[((arow * C_DIM + c) * PS + i) * XPAD + X] = s;
            }
        }
    }
}

// ---------------- pass 2: vertical fold + normalize + mean ------------------
__global__ void __launch_bounds__(544)
pass2_kernel(float* __restrict__ out) {
    const int t = blockIdx.y;
    const int y = blockIdx.x;
    const int x = threadIdx.x;
    if (x >= OUT_HW) return;

    // contributing patch rows: py = y+4-i, i = 0..4
    float cnt = 0.f;
    #pragma unroll
    for (int i = 0; i < PS; ++i)
        cnt += g_Acnt[((size_t)t * PW_DIM + (y + 4 - i)) * XPAD + x];
    const float inv = 1.0f / cnt;

    #pragma unroll
    for (int c = 0; c < C_DIM; ++c) {
        float s = 0.f;
        #pragma unroll
        for (int i = 0; i < PS; ++i) {
            const size_t arow = (size_t)t * PW_DIM + (y + 4 - i);
            s += g_A[((arow * C_DIM + c) * PS + i) * XPAD + x];
        }
        float v = s * inv + g_means[t * C_DIM + c];
        out[(((size_t)t * C_DIM + c) * OUT_HW + y) * OUT_HW + x] = v * 0.5f + 0.5f;
    }
}

// ---------------- launch ----------------
extern "C" void kernel_launch(void* const* d_in, const int* in_sizes, int n_in,
                              void* d_out, int out_size) {
    const float* noisy = (const float*)d_in[0];
    const float* deno  = (const float*)d_in[1];
    const float* pw    = (const float*)d_in[2];
    float* out = (float*)d_out;

    mean_stage1<<<6 * 64, 256>>>(noisy);
    mean_stage2<<<6, 64>>>();

    dim3 g1(NSEG, PW_DIM, T_DIM);            // 5 x 536 x 2 = 5360 blocks
    pass1_kernel<<<g1, 128>>>(deno, pw);

    dim3 g2(OUT_HW, T_DIM);                  // 532 x 2 = 1064 blocks
    pass2_kernel<<<g2, 544>>>(out);
}

// round 7
// speedup vs baseline: 3.8541x; 1.8917x over previous
#include <cuda_runtime.h>
#include <cuda_bf16.h>
#include <cstddef>
#include <cstdint>

// Problem constants (fixed by setup_inputs)
#define T_DIM   2
#define C_DIM   3
#define OUT_HW  532
#define PW_DIM  536
#define HW_PATCH (PW_DIM * PW_DIM)     // 287296
#define PDIM    75
#define PS      5
#define IMG_PIX (OUT_HW * OUT_HW)      // 283024

// Pass-1 tiling: 4 segments of 133 columns (4*133 = 532, no tail)
#define SEG    133
#define NSEGS  4
#define NROWS  4                        // patch rows per CTA (double-buffered)
#define NPATS  (SEG + 4)                // 137 patches staged per row
#define SBUF_F (NPATS * PDIM + 4)      // 10279 -> padded
#define SBUF_FP 10280
#define WBUF_F 140
#define XPAD   544                      // padded row width for A

#define P1_SMEM_FLOATS (2 * SBUF_FP + 2 * WBUF_F)
#define P1_SMEM_BYTES  (P1_SMEM_FLOATS * 4)     // 83360

// Intermediate buffers (device globals: no allocation allowed)
__device__ float g_A[(size_t)T_DIM * PW_DIM * C_DIM * PS * XPAD];   // ~35 MB
__device__ float g_Acnt[(size_t)T_DIM * PW_DIM * XPAD];             // ~2.3 MB
__device__ float g_partials[6 * 64];
__device__ float g_means[6];

// ---------------- cp.async helpers ----------------
__device__ __forceinline__ void cpa4(uint32_t dst, const void* src) {
    asm volatile("cp.async.ca.shared.global [%0], [%1], 4;\n" :: "r"(dst), "l"(src));
}
__device__ __forceinline__ void cpa16(uint32_t dst, const void* src) {
    asm volatile("cp.async.cg.shared.global [%0], [%1], 16;\n" :: "r"(dst), "l"(src));
}
__device__ __forceinline__ void cpa_commit() {
    asm volatile("cp.async.commit_group;\n");
}
template <int N>
__device__ __forceinline__ void cpa_wait() {
    asm volatile("cp.async.wait_group %0;\n" :: "n"(N));
}

// ---------------- mean reduction (deterministic, 2-stage, float4) ----------
__global__ void mean_stage1(const float* __restrict__ noisy) {
    const int NV = IMG_PIX / 4;               // 70756 float4 per (t,c)
    int tc  = blockIdx.x >> 6;                // t*3 + c
    int seg = blockIdx.x & 63;
    const float4* base = (const float4*)(noisy + (size_t)tc * IMG_PIX);
    const int per = (NV + 63) / 64;           // 1106
    int start = seg * per;
    int end   = start + per; if (end > NV) end = NV;
    float s = 0.f;
    for (int i = start + threadIdx.x; i < end; i += 256) {
        float4 v = base[i];
        s += (v.x + v.y) + (v.z + v.w);
    }
    __shared__ float red[256];
    red[threadIdx.x] = s;
    __syncthreads();
    for (int o = 128; o > 0; o >>= 1) {
        if (threadIdx.x < o) red[threadIdx.x] += red[threadIdx.x + o];
        __syncthreads();
    }
    if (threadIdx.x == 0) g_partials[blockIdx.x] = red[0];
}

__global__ void mean_stage2() {
    __shared__ float red[64];
    red[threadIdx.x] = g_partials[blockIdx.x * 64 + threadIdx.x];
    __syncthreads();
    if (threadIdx.x < 32) {
        float v = red[threadIdx.x] + red[threadIdx.x + 32];
        #pragma unroll
        for (int o = 16; o > 0; o >>= 1)
            v += __shfl_down_sync(0xffffffffu, v, o);
        if (threadIdx.x == 0)
            g_means[blockIdx.x] = (v / (float)IMG_PIX - 0.5f) * 2.0f;
    }
}

// ---------------- pass 1: horizontal fold, pipelined ------------------------
// A[t, py, c, i, X] = sum_j deno[t, py, X+4-j, c*25+i*5+j] * w[t, py, X+4-j]
// Acnt[t, py, X]    = sum_j w[t, py, X+4-j]
__global__ void __launch_bounds__(128)
pass1_kernel(const float* __restrict__ deno, const float* __restrict__ pw) {
    extern __shared__ float sm[];
    float* dbuf0 = sm;
    float* dbuf1 = sm + SBUF_FP;
    float* wbuf0 = sm + 2 * SBUF_FP;
    float* wbuf1 = wbuf0 + WBUF_F;

    const int t   = blockIdx.z;
    const int gy  = blockIdx.y;            // 0..133
    const int x0  = blockIdx.x * SEG;
    const int tid = threadIdx.x;
    const int py0 = gy * NROWS;

    // ---- stage one patch row into buffer bi via cp.async -------------------
    auto stage_row = [&](int r, int bi) {
        const int py = py0 + r;
        const size_t rowbase = (size_t)t * HW_PATCH + (size_t)py * PW_DIM + x0;
        const float* src  = deno + rowbase * PDIM;
        const float* wsrc = pw + rowbase;
        float* db = bi ? dbuf1 : dbuf0;
        float* wb = bi ? wbuf1 : wbuf0;

        const int a  = (int)(((uintptr_t)src >> 2) & 3);   // float misalignment
        const int e0 = (4 - a) & 3;                         // floats to 16B align
        uint32_t sb = (uint32_t)__cvta_generic_to_shared(db + a);
        const int n = NPATS * PDIM;                         // 10275
        if (tid < e0) cpa4(sb + tid * 4, src + tid);
        const int nb = (n - e0) >> 2;                       // float4 count
        const float* bsrc = src + e0;
        uint32_t bdst = sb + e0 * 4;
        for (int v = tid; v < nb; v += 128)
            cpa16(bdst + v * 16, bsrc + v * 4);
        const int done = e0 + nb * 4;
        if (tid < n - done) cpa4(sb + (done + tid) * 4, src + done + tid);
        // weights (scalar, 137 elems)
        uint32_t wsb = (uint32_t)__cvta_generic_to_shared(wb);
        for (int e = tid; e < NPATS; e += 128) cpa4(wsb + e * 4, wsrc + e);
    };

    // ---- compute one row from buffer bi ------------------------------------
    auto compute_row = [&](int r, int bi) {
        const int py = py0 + r;
        const size_t rowbase = (size_t)t * HW_PATCH + (size_t)py * PW_DIM + x0;
        const int shift = (int)((rowbase * PDIM) & 3);   // matches staging 'a'
        const float* db = (bi ? dbuf1 : dbuf0) + shift;
        const float* wb = bi ? wbuf1 : wbuf0;
        const size_t arow = (size_t)t * PW_DIM + py;

        #pragma unroll
        for (int pass = 0; pass < 2; ++pass) {
            const int col = pass == 0 ? tid : 128 + tid;
            if (pass == 1 && tid >= SEG - 128) break;    // cols 128..132
            const int X = x0 + col;
            float wr[PS];
            #pragma unroll
            for (int j = 0; j < PS; ++j) wr[j] = wb[col + 4 - j];
            float cnt = ((wr[0] + wr[1]) + (wr[2] + wr[3])) + wr[4];
            g_Acnt[arow * XPAD + X] = cnt;

            const float* b = db + col * PDIM;
            #pragma unroll
            for (int c = 0; c < C_DIM; ++c) {
                #pragma unroll
                for (int i = 0; i < PS; ++i) {
                    float s = 0.f;
                    #pragma unroll
                    for (int j = 0; j < PS; ++j)
                        s += b[(4 - j) * PDIM + c * 25 + i * 5 + j] * wr[j];
                    g_A[((arow * C_DIM + c) * PS + i) * XPAD + X] = s;
                }
            }
        }
    };

    // ---- pipeline ----------------------------------------------------------
    stage_row(0, 0);
    cpa_commit();
    #pragma unroll
    for (int r = 0; r < NROWS; ++r) {
        if (r + 1 < NROWS) {
            stage_row(r + 1, (r + 1) & 1);
            cpa_commit();
            cpa_wait<1>();          // row r complete
        } else {
            cpa_wait<0>();
        }
        __syncthreads();            // data visible to all threads
        compute_row(r, r & 1);
        __syncthreads();            // done reading before next overwrite
    }
}

// ---------------- pass 2: vertical fold + normalize + mean ------------------
__global__ void __launch_bounds__(544)
pass2_kernel(float* __restrict__ out) {
    const int t = blockIdx.y;
    const int y = blockIdx.x;
    const int x = threadIdx.x;
    if (x >= OUT_HW) return;

    float cnt = 0.f;
    #pragma unroll
    for (int i = 0; i < PS; ++i)
        cnt += g_Acnt[((size_t)t * PW_DIM + (y + 4 - i)) * XPAD + x];
    const float inv = 1.0f / cnt;

    #pragma unroll
    for (int c = 0; c < C_DIM; ++c) {
        float s = 0.f;
        #pragma unroll
        for (int i = 0; i < PS; ++i) {
            const size_t arow = (size_t)t * PW_DIM + (y + 4 - i);
            s += g_A[((arow * C_DIM + c) * PS + i) * XPAD + x];
        }
        float v = s * inv + g_means[t * C_DIM + c];
        out[(((size_t)t * C_DIM + c) * OUT_HW + y) * OUT_HW + x] = v * 0.5f + 0.5f;
    }
}

// ---------------- launch ----------------
extern "C" void kernel_launch(void* const* d_in, const int* in_sizes, int n_in,
                              void* d_out, int out_size) {
    const float* noisy = (const float*)d_in[0];
    const float* deno  = (const float*)d_in[1];
    const float* pw    = (const float*)d_in[2];
    float* out = (float*)d_out;

    cudaFuncSetAttribute(pass1_kernel,
                         cudaFuncAttributeMaxDynamicSharedMemorySize,
                         P1_SMEM_BYTES);

    mean_stage1<<<6 * 64, 256>>>(noisy);

    dim3 g1(NSEGS, PW_DIM / NROWS, T_DIM);   // 4 x 134 x 2 = 1072 blocks
    pass1_kernel<<<g1, 128, P1_SMEM_BYTES>>>(deno, pw);

    mean_stage2<<<6, 64>>>();

    dim3 g2(OUT_HW, T_DIM);                  // 532 x 2 = 1064 blocks
    pass2_kernel<<<g2, 544>>>(out);
}

// round 10
// speedup vs baseline: 4.0000x; 1.0379x over previous
#include <cuda_runtime.h>
#include <cuda_bf16.h>
#include <cstddef>
#include <cstdint>

// Problem constants (fixed by setup_inputs)
#define T_DIM   2
#define C_DIM   3
#define OUT_HW  532
#define PW_DIM  536
#define HW_PATCH (PW_DIM * PW_DIM)     // 287296
#define PDIM    75
#define PS      5
#define IMG_PIX (OUT_HW * OUT_HW)      // 283024

// Pass-1 tiling: 4 segments of 133 columns (4*133 = 532, no tail)
#define SEG    133
#define NSEGS  4
#define NROWS  4                        // patch rows per CTA (double-buffered)
#define NPATS  (SEG + 4)                // 137 patches staged per row
#define SBUF_F (NPATS * PDIM + 4)      // 10279 -> padded
#define SBUF_FP 10280
#define WBUF_F 140
#define XPAD   544                      // padded row width for A

#define P1_SMEM_FLOATS (2 * SBUF_FP + 2 * WBUF_F)
#define P1_SMEM_BYTES  (P1_SMEM_FLOATS * 4)     // 83360

// Intermediate buffers (device globals: no allocation allowed)
__device__ float g_A[(size_t)T_DIM * PW_DIM * C_DIM * PS * XPAD];   // ~35 MB
__device__ float g_Acnt[(size_t)T_DIM * PW_DIM * XPAD];             // ~2.3 MB
__device__ float g_partials[6 * 64];
__device__ float g_means[6];

// ---------------- cp.async helpers ----------------
__device__ __forceinline__ void cpa4(uint32_t dst, const void* src) {
    asm volatile("cp.async.ca.shared.global [%0], [%1], 4;\n" :: "r"(dst), "l"(src));
}
__device__ __forceinline__ void cpa16(uint32_t dst, const void* src) {
    asm volatile("cp.async.cg.shared.global [%0], [%1], 16;\n" :: "r"(dst), "l"(src));
}
__device__ __forceinline__ void cpa_commit() {
    asm volatile("cp.async.commit_group;\n");
}
template <int N>
__device__ __forceinline__ void cpa_wait() {
    asm volatile("cp.async.wait_group %0;\n" :: "n"(N));
}

// ---------------- mean reduction (deterministic, 2-stage, float4) ----------
__global__ void mean_stage1(const float* __restrict__ noisy) {
    const int NV = IMG_PIX / 4;               // 70756 float4 per (t,c)
    int tc  = blockIdx.x >> 6;                // t*3 + c
    int seg = blockIdx.x & 63;
    const float4* base = (const float4*)(noisy + (size_t)tc * IMG_PIX);
    const int per = (NV + 63) / 64;           // 1106
    int start = seg * per;
    int end   = start + per; if (end > NV) end = NV;
    float s = 0.f;
    for (int i = start + threadIdx.x; i < end; i += 256) {
        float4 v = base[i];
        s += (v.x + v.y) + (v.z + v.w);
    }
    __shared__ float red[256];
    red[threadIdx.x] = s;
    __syncthreads();
    for (int o = 128; o > 0; o >>= 1) {
        if (threadIdx.x < o) red[threadIdx.x] += red[threadIdx.x + o];
        __syncthreads();
    }
    if (threadIdx.x == 0) g_partials[blockIdx.x] = red[0];
}

__global__ void mean_stage2() {
    __shared__ float red[64];
    red[threadIdx.x] = g_partials[blockIdx.x * 64 + threadIdx.x];
    __syncthreads();
    if (threadIdx.x < 32) {
        float v = red[threadIdx.x] + red[threadIdx.x + 32];
        #pragma unroll
        for (int o = 16; o > 0; o >>= 1)
            v += __shfl_down_sync(0xffffffffu, v, o);
        if (threadIdx.x == 0)
            g_means[blockIdx.x] = (v / (float)IMG_PIX - 0.5f) * 2.0f;
    }
}

// ---------------- pass 1: horizontal fold, pipelined ------------------------
// A[t, py, c, i, X] = sum_j deno[t, py, X+4-j, c*25+i*5+j] * w[t, py, X+4-j]
// Acnt[t, py, X]    = sum_j w[t, py, X+4-j]
__global__ void __launch_bounds__(128)
pass1_kernel(const float* __restrict__ deno, const float* __restrict__ pw) {
    extern __shared__ float sm[];
    float* dbuf0 = sm;
    float* dbuf1 = sm + SBUF_FP;
    float* wbuf0 = sm + 2 * SBUF_FP;
    float* wbuf1 = wbuf0 + WBUF_F;

    const int t   = blockIdx.z;
    const int gy  = blockIdx.y;            // 0..133
    const int x0  = blockIdx.x * SEG;
    const int tid = threadIdx.x;
    const int py0 = gy * NROWS;

    // ---- stage one patch row into buffer bi via cp.async -------------------
    auto stage_row = [&](int r, int bi) {
        const int py = py0 + r;
        const size_t rowbase = (size_t)t * HW_PATCH + (size_t)py * PW_DIM + x0;
        const float* src  = deno + rowbase * PDIM;
        const float* wsrc = pw + rowbase;
        float* db = bi ? dbuf1 : dbuf0;
        float* wb = bi ? wbuf1 : wbuf0;

        const int a  = (int)(((uintptr_t)src >> 2) & 3);   // float misalignment
        const int e0 = (4 - a) & 3;                         // floats to 16B align
        uint32_t sb = (uint32_t)__cvta_generic_to_shared(db + a);
        const int n = NPATS * PDIM;                         // 10275
        if (tid < e0) cpa4(sb + tid * 4, src + tid);
        const int nb = (n - e0) >> 2;                       // float4 count
        const float* bsrc = src + e0;
        uint32_t bdst = sb + e0 * 4;
        for (int v = tid; v < nb; v += 128)
            cpa16(bdst + v * 16, bsrc + v * 4);
        const int done = e0 + nb * 4;
        if (tid < n - done) cpa4(sb + (done + tid) * 4, src + done + tid);
        // weights (scalar, 137 elems)
        uint32_t wsb = (uint32_t)__cvta_generic_to_shared(wb);
        for (int e = tid; e < NPATS; e += 128) cpa4(wsb + e * 4, wsrc + e);
    };

    // ---- compute one row from buffer bi ------------------------------------
    auto compute_row = [&](int r, int bi) {
        const int py = py0 + r;
        const size_t rowbase = (size_t)t * HW_PATCH + (size_t)py * PW_DIM + x0;
        const int shift = (int)((rowbase * PDIM) & 3);   // matches staging 'a'
        const float* db = (bi ? dbuf1 : dbuf0) + shift;
        const float* wb = bi ? wbuf1 : wbuf0;
        const size_t arow = (size_t)t * PW_DIM + py;

        #pragma unroll
        for (int pass = 0; pass < 2; ++pass) {
            const int col = pass == 0 ? tid : 128 + tid;
            if (pass == 1 && tid >= SEG - 128) break;    // cols 128..132
            const int X = x0 + col;
            float wr[PS];
            #pragma unroll
            for (int j = 0; j < PS; ++j) wr[j] = wb[col + 4 - j];
            float cnt = ((wr[0] + wr[1]) + (wr[2] + wr[3])) + wr[4];
            g_Acnt[arow * XPAD + X] = cnt;

            const float* b = db + col * PDIM;
            #pragma unroll
            for (int c = 0; c < C_DIM; ++c) {
                #pragma unroll
                for (int i = 0; i < PS; ++i) {
                    float s = 0.f;
                    #pragma unroll
                    for (int j = 0; j < PS; ++j)
                        s += b[(4 - j) * PDIM + c * 25 + i * 5 + j] * wr[j];
                    g_A[((arow * C_DIM + c) * PS + i) * XPAD + X] = s;
                }
            }
        }
    };

    // ---- pipeline ----------------------------------------------------------
    stage_row(0, 0);
    cpa_commit();
    #pragma unroll
    for (int r = 0; r < NROWS; ++r) {
        if (r + 1 < NROWS) {
            stage_row(r + 1, (r + 1) & 1);
            cpa_commit();
            cpa_wait<1>();          // row r complete
        } else {
            cpa_wait<0>();
        }
        __syncthreads();            // data visible to all threads
        compute_row(r, r & 1);
        __syncthreads();            // done reading before next overwrite
    }
}

// ---------------- pass 2: vertical fold + normalize + mean (float4) --------
__global__ void __launch_bounds__(532)
pass2_kernel(float* __restrict__ out) {
    const int t  = blockIdx.y;
    const int y  = blockIdx.x * 4 + threadIdx.y;   // output row
    const int x4 = threadIdx.x;                    // float4 index, 0..132

    const float4* A4 = (const float4*)g_A;
    const float4* C4 = (const float4*)g_Acnt;
    const size_t xq = x4;                           // float4 units; XPAD/4 = 136

    float4 cnt = make_float4(0.f, 0.f, 0.f, 0.f);
    #pragma unroll
    for (int i = 0; i < PS; ++i) {
        float4 v = C4[((size_t)t * PW_DIM + (y + 4 - i)) * (XPAD / 4) + xq];
        cnt.x += v.x; cnt.y += v.y; cnt.z += v.z; cnt.w += v.w;
    }
    float4 inv;
    inv.x = 1.0f / cnt.x; inv.y = 1.0f / cnt.y;
    inv.z = 1.0f / cnt.z; inv.w = 1.0f / cnt.w;

    #pragma unroll
    for (int c = 0; c < C_DIM; ++c) {
        float4 s = make_float4(0.f, 0.f, 0.f, 0.f);
        #pragma unroll
        for (int i = 0; i < PS; ++i) {
            const size_t arow = (size_t)t * PW_DIM + (y + 4 - i);
            float4 v = A4[((arow * C_DIM + c) * PS + i) * (XPAD / 4) + xq];
            s.x += v.x; s.y += v.y; s.z += v.z; s.w += v.w;
        }
        const float m = g_means[t * C_DIM + c];
        float4 o;
        o.x = (s.x * inv.x + m) * 0.5f + 0.5f;
        o.y = (s.y * inv.y + m) * 0.5f + 0.5f;
        o.z = (s.z * inv.z + m) * 0.5f + 0.5f;
        o.w = (s.w * inv.w + m) * 0.5f + 0.5f;
        ((float4*)out)[((((size_t)t * C_DIM + c) * OUT_HW + y) * OUT_HW) / 4 + xq] = o;
    }
}

// ---------------- launch ----------------
extern "C" void kernel_launch(void* const* d_in, const int* in_sizes, int n_in,
                              void* d_out, int out_size) {
    const float* noisy = (const float*)d_in[0];
    const float* deno  = (const float*)d_in[1];
    const float* pw    = (const float*)d_in[2];
    float* out = (float*)d_out;

    cudaFuncSetAttribute(pass1_kernel,
                         cudaFuncAttributeMaxDynamicSharedMemorySize,
                         P1_SMEM_BYTES);

    mean_stage1<<<6 * 64, 256>>>(noisy);
    mean_stage2<<<6, 64>>>();

    dim3 g1(NSEGS, PW_DIM / NROWS, T_DIM);   // 4 x 134 x 2 = 1072 blocks
    pass1_kernel<<<g1, 128, P1_SMEM_BYTES>>>(deno, pw);

    dim3 g2(OUT_HW / 4, T_DIM);              // 133 x 2 blocks
    dim3 b2(OUT_HW / 4, 4);                  // 133 x 4 = 532 threads
    pass2_kernel<<<g2, b2>>>(out);
}